// round 1
// baseline (speedup 1.0000x reference)
#include <cuda_runtime.h>
#include <math.h>

#define N_NODE 40000
#define N_REL  2000
#define T      600000
#define DIM    128
#define F3     384
#define NP     64
#define EPSF   1e-12f

// ---------------- scratch (device globals; no allocation) ----------------
__device__ float    g_outE[N_NODE * F3];
__device__ float    g_outR[N_NODE * F3];
__device__ float    g_acc[N_NODE * DIM];
__device__ float    g_pf[N_NODE * F3];
__device__ float    g_pa[N_NODE * NP];
__device__ float    g_nrm[N_NODE];
__device__ float    g_alpha[T];
__device__ float    g_atte[4 * T];
__device__ unsigned g_rowmax[4 * N_NODE];
__device__ float    g_rowsum[4 * N_NODE];
__device__ int      g_degE[N_NODE];
__device__ int      g_degR[N_NODE];
__device__ float    g_relNorm[N_REL];
__device__ float    g_dotRel[N_REL * 4];
__device__ float    g_pninv[NP];

// ---------------- helpers ----------------
__device__ __forceinline__ unsigned fenc(float f) {
    unsigned u = __float_as_uint(f);
    return (u & 0x80000000u) ? ~u : (u | 0x80000000u);
}
__device__ __forceinline__ float fdec(unsigned u) {
    return __uint_as_float((u & 0x80000000u) ? (u ^ 0x80000000u) : ~u);
}
__device__ __forceinline__ float wredsum(float v) {
#pragma unroll
    for (int o = 16; o; o >>= 1) v += __shfl_xor_sync(0xffffffffu, v, o);
    return v;
}
__device__ __forceinline__ float wredmax(float v) {
#pragma unroll
    for (int o = 16; o; o >>= 1) v = fmaxf(v, __shfl_xor_sync(0xffffffffu, v, o));
    return v;
}
__device__ __forceinline__ void red_v4(float* p, float4 v) {
    asm volatile("red.global.add.v4.f32 [%0], {%1, %2, %3, %4};"
                 :: "l"(p), "f"(v.x), "f"(v.y), "f"(v.z), "f"(v.w) : "memory");
}
__device__ __forceinline__ float dot4(float4 a, float4 b) {
    return a.x * b.x + a.y * b.y + a.z * b.z + a.w * b.w;
}

// ---------------- init ----------------
__global__ void k_init() {
    int i = blockIdx.x * blockDim.x + threadIdx.x;
    if (i < 4 * N_NODE) { g_rowmax[i] = fenc(-3.4e38f); g_rowsum[i] = 0.f; }
    if (i < N_NODE) { g_degE[i] = 0; g_degR[i] = 0; }
}
__global__ void k_zero_acc() {
    int i = blockIdx.x * blockDim.x + threadIdx.x;
    if (i < N_NODE * DIM) g_acc[i] = 0.f;
}

// per-relation: norm and dot with the 4 attention vectors
__global__ void k_rel_prep(const float* __restrict__ rel_emb,
                           const float* __restrict__ eattn,
                           const float* __restrict__ rattn) {
    int w = blockIdx.x * 8 + (threadIdx.x >> 5);
    if (w >= N_REL) return;
    int lane = threadIdx.x & 31;
    float4 v  = *(const float4*)(rel_emb + w * DIM + lane * 4);
    float4 a0 = *(const float4*)(eattn + lane * 4);
    float4 a1 = *(const float4*)(eattn + 128 + lane * 4);
    float4 a2 = *(const float4*)(rattn + lane * 4);
    float4 a3 = *(const float4*)(rattn + 128 + lane * 4);
    float ss = wredsum(dot4(v, v));
    float d0 = wredsum(dot4(v, a0));
    float d1 = wredsum(dot4(v, a1));
    float d2 = wredsum(dot4(v, a2));
    float d3 = wredsum(dot4(v, a3));
    if (lane == 0) {
        g_relNorm[w] = sqrtf(ss);
        g_dotRel[w * 4 + 0] = d0; g_dotRel[w * 4 + 1] = d1;
        g_dotRel[w * 4 + 2] = d2; g_dotRel[w * 4 + 3] = d3;
    }
}

// per-edge alpha + attention-logit row-max (4 combos)
__global__ void k_alpha_max(const int* __restrict__ row, const int* __restrict__ rid,
                            const float* __restrict__ rval) {
    int t = blockIdx.x * blockDim.x + threadIdx.x;
    if (t >= T) return;
    int r = row[t], rd = rid[t];
    float rv = rval[t];
    float a = rv / fmaxf(rv * g_relNorm[rd], EPSF);
    g_alpha[t] = a;
    float4 dr = *(const float4*)(g_dotRel + rd * 4);
    atomicMax(&g_rowmax[0 * N_NODE + r], fenc(a * dr.x));
    atomicMax(&g_rowmax[1 * N_NODE + r], fenc(a * dr.y));
    atomicMax(&g_rowmax[2 * N_NODE + r], fenc(a * dr.z));
    atomicMax(&g_rowmax[3 * N_NODE + r], fenc(a * dr.w));
}

__global__ void k_expsum(const int* __restrict__ row, const int* __restrict__ rid) {
    int t = blockIdx.x * blockDim.x + threadIdx.x;
    if (t >= T) return;
    int r = row[t], rd = rid[t];
    float a = g_alpha[t];
    float4 dr = *(const float4*)(g_dotRel + rd * 4);
    float s[4] = { a * dr.x, a * dr.y, a * dr.z, a * dr.w };
#pragma unroll
    for (int c = 0; c < 4; c++) {
        float e = expf(s[c] - fdec(g_rowmax[c * N_NODE + r]));
        g_atte[c * T + t] = e;
        atomicAdd(&g_rowsum[c * N_NODE + r], e);
    }
}

__global__ void k_deg(const int* __restrict__ rows, int which) {
    int t = blockIdx.x * blockDim.x + threadIdx.x;
    if (t >= T) return;
    atomicAdd((which ? g_degR : g_degE) + rows[t], 1);
}

// neighbor-sum (mean later): warp per edge
__global__ void k_avg(const int* __restrict__ rows, const int* __restrict__ cols,
                      const float* __restrict__ emb) {
    int e = blockIdx.x * 8 + (threadIdx.x >> 5);
    if (e >= T) return;
    int lane = threadIdx.x & 31;
    int r = rows[e], c = cols[e];
    float4 v = *(const float4*)(emb + c * DIM + lane * 4);
    red_v4(&g_acc[r * DIM + lane * 4], v);
}

__global__ void k_tanh_avg(int enc) {
    int i = blockIdx.x * blockDim.x + threadIdx.x;
    if (i >= N_NODE * DIM) return;
    int node = i >> 7, d = i & 127;
    int dg = enc ? g_degR[node] : g_degE[node];
    float f = (dg > 0) ? g_acc[i] / (float)dg : 0.f;
    (enc ? g_outR : g_outE)[node * F3 + d] = tanhf(f);
}

// heavy pass: Householder reflection + attention-weighted scatter. warp per edge.
__global__ void k_edge(const int* __restrict__ row, const int* __restrict__ col,
                       const int* __restrict__ rid, const float* __restrict__ rel_emb,
                       int enc, int l) {
    int e = blockIdx.x * 8 + (threadIdx.x >> 5);
    if (e >= T) return;
    int lane = threadIdx.x & 31;
    const float* outp = enc ? g_outR : g_outE;
    const float* src = outp + l * DIM;
    int c = enc * 2 + l;
    int r = row[e], cl = col[e], rd = rid[e];
    float a = g_alpha[e];
    float w = g_atte[c * T + e] / g_rowsum[c * N_NODE + r];
    float4 h  = *(const float4*)(src + cl * F3 + lane * 4);
    float4 tr = *(const float4*)(rel_emb + rd * DIM + lane * 4);
    tr.x *= a; tr.y *= a; tr.z *= a; tr.w *= a;
    float d = wredsum(dot4(h, tr));
    float c2 = -2.f * w * d;
    float4 v;
    v.x = w * h.x + c2 * tr.x; v.y = w * h.y + c2 * tr.y;
    v.z = w * h.z + c2 * tr.z; v.w = w * h.w + c2 * tr.w;
    red_v4(&g_acc[r * DIM + lane * 4], v);
}

__global__ void k_tanh_layer(int enc, int l) {
    int i = blockIdx.x * blockDim.x + threadIdx.x;
    if (i >= N_NODE * DIM) return;
    int node = i >> 7, d = i & 127;
    (enc ? g_outR : g_outE)[node * F3 + (l + 1) * DIM + d] = tanhf(g_acc[i]);
}

// ---------------- epilogue ----------------
__global__ void k_rownorm(int enc) {
    int n = blockIdx.x * 8 + (threadIdx.x >> 5);
    if (n >= N_NODE) return;
    int lane = threadIdx.x & 31;
    const float* p = (enc ? g_outR : g_outE) + n * F3;
    float ss = 0.f;
#pragma unroll
    for (int j = 0; j < 3; j++) {
        float4 v = *(const float4*)(p + j * 128 + lane * 4);
        ss += dot4(v, v);
    }
    ss = wredsum(ss);
    if (lane == 0) g_nrm[n] = fmaxf(sqrtf(ss), EPSF);
}

__global__ void k_pninv(const float* __restrict__ proxy) {
    int j = blockIdx.x * 8 + (threadIdx.x >> 5);
    if (j >= NP) return;
    int lane = threadIdx.x & 31;
    float ss = 0.f;
#pragma unroll
    for (int k = 0; k < 3; k++) {
        float4 v = *(const float4*)(proxy + j * F3 + k * 128 + lane * 4);
        ss += dot4(v, v);
    }
    ss = wredsum(ss);
    if (lane == 0) g_pninv[j] = 1.f / fmaxf(sqrtf(ss), EPSF);
}

// logits = out @ normalize(proxy)^T  (raw, norm-divide folded into softmax)
__global__ void k_gemmA(const float* __restrict__ proxy, int enc) {
    __shared__ float As[16][64];
    __shared__ float Bs[16][64];
    const float* A = enc ? g_outR : g_outE;
    int bm = blockIdx.x * 64;
    int tid = threadIdx.x, tx = tid & 15, ty = tid >> 4;
    float acc[4][4] = {};
    for (int k0 = 0; k0 < F3; k0 += 16) {
        {
            int i = tid >> 2, kk = (tid & 3) << 2;
            float4 v = *(const float4*)(A + (bm + i) * F3 + k0 + kk);
            As[kk + 0][i] = v.x; As[kk + 1][i] = v.y; As[kk + 2][i] = v.z; As[kk + 3][i] = v.w;
            // B[k][n] = proxy[n][k] * pninv[n]
            int n = tid >> 2;
            float s = g_pninv[n];
            float4 b = *(const float4*)(proxy + n * F3 + k0 + kk);
            Bs[kk + 0][n] = b.x * s; Bs[kk + 1][n] = b.y * s;
            Bs[kk + 2][n] = b.z * s; Bs[kk + 3][n] = b.w * s;
        }
        __syncthreads();
#pragma unroll
        for (int kk = 0; kk < 16; kk++) {
            float4 a4 = *(float4*)&As[kk][ty << 2];
            float4 b4 = *(float4*)&Bs[kk][tx << 2];
            float av[4] = { a4.x, a4.y, a4.z, a4.w };
            float bv[4] = { b4.x, b4.y, b4.z, b4.w };
#pragma unroll
            for (int r = 0; r < 4; r++)
#pragma unroll
                for (int cc = 0; cc < 4; cc++) acc[r][cc] += av[r] * bv[cc];
        }
        __syncthreads();
    }
#pragma unroll
    for (int r = 0; r < 4; r++) {
        int m = bm + (ty << 2) + r, n = tx << 2;
        float4 o = make_float4(acc[r][0], acc[r][1], acc[r][2], acc[r][3]);
        *(float4*)(g_pa + m * NP + n) = o;
    }
}

__global__ void k_softmax() {
    int n = blockIdx.x * 8 + (threadIdx.x >> 5);
    if (n >= N_NODE) return;
    int lane = threadIdx.x & 31;
    float inv = 1.f / g_nrm[n];
    float v0 = g_pa[n * NP + lane] * inv;
    float v1 = g_pa[n * NP + lane + 32] * inv;
    float m = wredmax(fmaxf(v0, v1));
    float e0 = expf(v0 - m), e1 = expf(v1 - m);
    float s = wredsum(e0 + e1);
    float is = 1.f / s;
    g_pa[n * NP + lane] = e0 * is;
    g_pa[n * NP + lane + 32] = e1 * is;
}

// pf = out - pa @ proxy     (M=40000, N=384, K=64)
__global__ void k_gemmB(const float* __restrict__ proxy, int enc) {
    __shared__ float As[16][64];
    __shared__ float Bs[16][64];
    int bm = blockIdx.y * 64, bn = blockIdx.x * 64;
    int tid = threadIdx.x, tx = tid & 15, ty = tid >> 4;
    float acc[4][4] = {};
    for (int k0 = 0; k0 < NP; k0 += 16) {
        {
            int i = tid >> 2, kk = (tid & 3) << 2;
            float4 v = *(const float4*)(g_pa + (bm + i) * NP + k0 + kk);
            As[kk + 0][i] = v.x; As[kk + 1][i] = v.y; As[kk + 2][i] = v.z; As[kk + 3][i] = v.w;
            int kb = tid >> 4, n4 = (tid & 15) << 2;
            *(float4*)&Bs[kb][n4] = *(const float4*)(proxy + (k0 + kb) * F3 + bn + n4);
        }
        __syncthreads();
#pragma unroll
        for (int kk = 0; kk < 16; kk++) {
            float4 a4 = *(float4*)&As[kk][ty << 2];
            float4 b4 = *(float4*)&Bs[kk][tx << 2];
            float av[4] = { a4.x, a4.y, a4.z, a4.w };
            float bv[4] = { b4.x, b4.y, b4.z, b4.w };
#pragma unroll
            for (int r = 0; r < 4; r++)
#pragma unroll
                for (int cc = 0; cc < 4; cc++) acc[r][cc] += av[r] * bv[cc];
        }
        __syncthreads();
    }
    const float* outp = enc ? g_outR : g_outE;
#pragma unroll
    for (int r = 0; r < 4; r++) {
        int m = bm + (ty << 2) + r, n = bn + (tx << 2);
        float4 o = *(const float4*)(outp + m * F3 + n);
        float4 v = make_float4(o.x - acc[r][0], o.y - acc[r][1],
                               o.z - acc[r][2], o.w - acc[r][3]);
        *(float4*)(g_pf + m * F3 + n) = v;
    }
}

// g = sigmoid(pf @ gate + bias); res = g*out + (1-g)*pf  -> d_out
__global__ void k_gemmC(const float* __restrict__ gate, const float* __restrict__ bias,
                        int enc, float* __restrict__ dout) {
    __shared__ float As[16][64];
    __shared__ float Bs[16][64];
    int bm = blockIdx.y * 64, bn = blockIdx.x * 64;
    int tid = threadIdx.x, tx = tid & 15, ty = tid >> 4;
    float acc[4][4] = {};
    for (int k0 = 0; k0 < F3; k0 += 16) {
        {
            int i = tid >> 2, kk = (tid & 3) << 2;
            float4 v = *(const float4*)(g_pf + (bm + i) * F3 + k0 + kk);
            As[kk + 0][i] = v.x; As[kk + 1][i] = v.y; As[kk + 2][i] = v.z; As[kk + 3][i] = v.w;
            int kb = tid >> 4, n4 = (tid & 15) << 2;
            *(float4*)&Bs[kb][n4] = *(const float4*)(gate + (k0 + kb) * F3 + bn + n4);
        }
        __syncthreads();
#pragma unroll
        for (int kk = 0; kk < 16; kk++) {
            float4 a4 = *(float4*)&As[kk][ty << 2];
            float4 b4 = *(float4*)&Bs[kk][tx << 2];
            float av[4] = { a4.x, a4.y, a4.z, a4.w };
            float bv[4] = { b4.x, b4.y, b4.z, b4.w };
#pragma unroll
            for (int r = 0; r < 4; r++)
#pragma unroll
                for (int cc = 0; cc < 4; cc++) acc[r][cc] += av[r] * bv[cc];
        }
        __syncthreads();
    }
    const float* outp = enc ? g_outR : g_outE;
#pragma unroll
    for (int r = 0; r < 4; r++) {
        int m = bm + (ty << 2) + r, n = bn + (tx << 2);
        float4 o = *(const float4*)(outp + m * F3 + n);
        float4 p = *(const float4*)(g_pf + m * F3 + n);
        float4 res;
        {
            float z = acc[r][0] + bias[n + 0]; float g = 1.f / (1.f + expf(-z));
            res.x = g * o.x + (1.f - g) * p.x;
            z = acc[r][1] + bias[n + 1]; g = 1.f / (1.f + expf(-z));
            res.y = g * o.y + (1.f - g) * p.y;
            z = acc[r][2] + bias[n + 2]; g = 1.f / (1.f + expf(-z));
            res.z = g * o.z + (1.f - g) * p.z;
            z = acc[r][3] + bias[n + 3]; g = 1.f / (1.f + expf(-z));
            res.w = g * o.w + (1.f - g) * p.w;
        }
        *(float4*)(dout + m * 768 + enc * F3 + n) = res;
    }
}

// ---------------- host ----------------
extern "C" void kernel_launch(void* const* d_in, const int* in_sizes, int n_in,
                              void* d_out, int out_size) {
    const int*   ent_adj = (const int*)d_in[0];
    const int*   rel_adj = (const int*)d_in[1];
    const int*   adj     = (const int*)d_in[4];
    const int*   r_index = (const int*)d_in[5];
    const float* r_val   = (const float*)d_in[6];
    const float* ent_emb = (const float*)d_in[9];
    const float* rel_emb = (const float*)d_in[10];
    const float* e_attn  = (const float*)d_in[11];
    const float* e_gate  = (const float*)d_in[12];
    const float* e_proxy = (const float*)d_in[13];
    const float* e_bias  = (const float*)d_in[14];
    const float* r_attn  = (const float*)d_in[15];
    const float* r_gate  = (const float*)d_in[16];
    const float* r_proxy = (const float*)d_in[17];
    const float* r_bias  = (const float*)d_in[18];
    float* out = (float*)d_out;

    const int* aRow = adj;
    const int* aCol = adj + T;
    const int* rid  = r_index + T;

    k_init<<<625, 256>>>();
    k_rel_prep<<<250, 256>>>(rel_emb, e_attn, r_attn);
    k_alpha_max<<<2344, 256>>>(aRow, rid, r_val);
    k_expsum<<<2344, 256>>>(aRow, rid);
    k_deg<<<2344, 256>>>(ent_adj, 0);
    k_deg<<<2344, 256>>>(rel_adj, 1);

    // initial averaged features
    k_zero_acc<<<20000, 256>>>();
    k_avg<<<75000, 256>>>(ent_adj, ent_adj + T, ent_emb);
    k_tanh_avg<<<20000, 256>>>(0);
    k_zero_acc<<<20000, 256>>>();
    k_avg<<<75000, 256>>>(rel_adj, rel_adj + T, rel_emb);
    k_tanh_avg<<<20000, 256>>>(1);

    // graph attention layers
    for (int enc = 0; enc < 2; enc++)
        for (int l = 0; l < 2; l++) {
            k_zero_acc<<<20000, 256>>>();
            k_edge<<<75000, 256>>>(aRow, aCol, rid, rel_emb, enc, l);
            k_tanh_layer<<<20000, 256>>>(enc, l);
        }

    // proxy/gate epilogue per encoder
    for (int enc = 0; enc < 2; enc++) {
        const float* proxy = enc ? r_proxy : e_proxy;
        const float* gate  = enc ? r_gate  : e_gate;
        const float* bias  = enc ? r_bias  : e_bias;
        k_rownorm<<<5000, 256>>>(enc);
        k_pninv<<<8, 256>>>(proxy);
        k_gemmA<<<625, 256>>>(proxy, enc);
        k_softmax<<<5000, 256>>>();
        dim3 gB(6, 625);
        k_gemmB<<<gB, 256>>>(proxy, enc);
        k_gemmC<<<gB, 256>>>(gate, bias, enc, out);
    }
}

// round 2
// speedup vs baseline: 1.3221x; 1.3221x over previous
#include <cuda_runtime.h>
#include <math.h>

#define N_NODE 40000
#define N_REL  2000
#define T      600000
#define DIM    128
#define F3     384
#define NP     64
#define EPSF   1e-12f
#define SCAN_B ((N_NODE + 255) / 256)   // 157

// ---------------- scratch (device globals; no allocation) ----------------
__device__ int    g_cnt[3 * N_NODE];
__device__ int    g_rowptr[3 * N_NODE];
__device__ int    g_cur[3 * N_NODE];
__device__ int    g_bsum[3 * 256];
__device__ int    g_sColE[T];
__device__ int    g_sColR[T];
__device__ int    g_sColA[T];
__device__ int    g_sRidA[T];
__device__ float  g_sAlpha[T];
__device__ float4 g_sW[T];

__device__ float g_outE[N_NODE * F3];
__device__ float g_outR[N_NODE * F3];
__device__ float g_pf[N_NODE * F3];
__device__ float g_pa[N_NODE * NP];
__device__ float g_nrm[N_NODE];
__device__ float g_relNorm[N_REL];
__device__ float g_dotRel[N_REL * 4];
__device__ float g_pninv[NP];

// ---------------- helpers ----------------
__device__ __forceinline__ float wredsum(float v) {
#pragma unroll
    for (int o = 16; o; o >>= 1) v += __shfl_xor_sync(0xffffffffu, v, o);
    return v;
}
__device__ __forceinline__ float wredmax(float v) {
#pragma unroll
    for (int o = 16; o; o >>= 1) v = fmaxf(v, __shfl_xor_sync(0xffffffffu, v, o));
    return v;
}
__device__ __forceinline__ float dot4(float4 a, float4 b) {
    return a.x * b.x + a.y * b.y + a.z * b.z + a.w * b.w;
}

// ---------------- CSR build ----------------
__global__ void k_zero_cnt() {
    int i = blockIdx.x * blockDim.x + threadIdx.x;
    if (i < 3 * N_NODE) g_cnt[i] = 0;
}
__global__ void k_hist(const int* __restrict__ rows, int sel) {
    int t = blockIdx.x * blockDim.x + threadIdx.x;
    if (t < T) atomicAdd(&g_cnt[sel * N_NODE + rows[t]], 1);
}
__global__ void k_scan1(int sel) {
    __shared__ int sh[256];
    int tid = threadIdx.x;
    int i = blockIdx.x * 256 + tid;
    int v = (i < N_NODE) ? g_cnt[sel * N_NODE + i] : 0;
    int x = v;
    sh[tid] = x; __syncthreads();
#pragma unroll
    for (int o = 1; o < 256; o <<= 1) {
        int t = (tid >= o) ? sh[tid - o] : 0;
        __syncthreads();
        x += t; sh[tid] = x;
        __syncthreads();
    }
    if (i < N_NODE) g_rowptr[sel * N_NODE + i] = x - v;  // exclusive
    if (tid == 255) g_bsum[sel * 256 + blockIdx.x] = x;  // block total
}
__global__ void k_scan2(int sel) {
    __shared__ int sh[256];
    int tid = threadIdx.x;
    int v = (tid < SCAN_B) ? g_bsum[sel * 256 + tid] : 0;
    int x = v;
    sh[tid] = x; __syncthreads();
#pragma unroll
    for (int o = 1; o < 256; o <<= 1) {
        int t = (tid >= o) ? sh[tid - o] : 0;
        __syncthreads();
        x += t; sh[tid] = x;
        __syncthreads();
    }
    g_bsum[sel * 256 + tid] = x - v;  // exclusive block offsets
}
__global__ void k_scan3(int sel) {
    int i = blockIdx.x * blockDim.x + threadIdx.x;
    if (i >= N_NODE) return;
    int val = g_rowptr[sel * N_NODE + i] + g_bsum[sel * 256 + (i >> 8)];
    g_rowptr[sel * N_NODE + i] = val;
    g_cur[sel * N_NODE + i] = val;
}
__global__ void k_scatter_col(const int* __restrict__ rows, const int* __restrict__ cols,
                              int sel) {
    int t = blockIdx.x * blockDim.x + threadIdx.x;
    if (t >= T) return;
    int pos = atomicAdd(&g_cur[sel * N_NODE + rows[t]], 1);
    (sel == 0 ? g_sColE : g_sColR)[pos] = cols[t];
}
__global__ void k_scatterA(const int* __restrict__ rows, const int* __restrict__ cols,
                           const int* __restrict__ rid, const float* __restrict__ rval) {
    int t = blockIdx.x * blockDim.x + threadIdx.x;
    if (t >= T) return;
    int pos = atomicAdd(&g_cur[2 * N_NODE + rows[t]], 1);
    int rd = rid[t];
    float rv = rval[t];
    g_sColA[pos] = cols[t];
    g_sRidA[pos] = rd;
    g_sAlpha[pos] = rv / fmaxf(rv * g_relNorm[rd], EPSF);
}

// per-relation: norm and dot with the 4 attention vectors
__global__ void k_rel_prep(const float* __restrict__ rel_emb,
                           const float* __restrict__ eattn,
                           const float* __restrict__ rattn) {
    int w = blockIdx.x * 8 + (threadIdx.x >> 5);
    if (w >= N_REL) return;
    int lane = threadIdx.x & 31;
    float4 v  = *(const float4*)(rel_emb + w * DIM + lane * 4);
    float4 a0 = *(const float4*)(eattn + lane * 4);
    float4 a1 = *(const float4*)(eattn + 128 + lane * 4);
    float4 a2 = *(const float4*)(rattn + lane * 4);
    float4 a3 = *(const float4*)(rattn + 128 + lane * 4);
    float ss = wredsum(dot4(v, v));
    float d0 = wredsum(dot4(v, a0));
    float d1 = wredsum(dot4(v, a1));
    float d2 = wredsum(dot4(v, a2));
    float d3 = wredsum(dot4(v, a3));
    if (lane == 0) {
        g_relNorm[w] = sqrtf(ss);
        g_dotRel[w * 4 + 0] = d0; g_dotRel[w * 4 + 1] = d1;
        g_dotRel[w * 4 + 2] = d2; g_dotRel[w * 4 + 3] = d3;
    }
}

// gather-mean + tanh: warp per node
__global__ void k_avg_csr(const float* __restrict__ emb, int sel) {
    int n = blockIdx.x * 8 + (threadIdx.x >> 5);
    if (n >= N_NODE) return;
    int lane = threadIdx.x & 31;
    int start = g_rowptr[sel * N_NODE + n];
    int deg = g_cnt[sel * N_NODE + n];
    const int* scol = sel == 0 ? g_sColE : g_sColR;
    float4 acc = make_float4(0.f, 0.f, 0.f, 0.f);
    for (int j = start; j < start + deg; j++) {
        int c = scol[j];
        float4 v = *(const float4*)(emb + c * DIM + lane * 4);
        acc.x += v.x; acc.y += v.y; acc.z += v.z; acc.w += v.w;
    }
    float inv = deg > 0 ? 1.f / (float)deg : 0.f;
    float* dst = (sel == 0 ? g_outE : g_outR) + n * F3 + lane * 4;
    dst[0] = tanhf(acc.x * inv);
    dst[1] = tanhf(acc.y * inv);
    dst[2] = tanhf(acc.z * inv);
    dst[3] = tanhf(acc.w * inv);
}

// per-node edge-attention softmax for all 4 (enc,layer) combos
__global__ void k_att_softmax() {
    int n = blockIdx.x * 8 + (threadIdx.x >> 5);
    if (n >= N_NODE) return;
    int lane = threadIdx.x & 31;
    int start = g_rowptr[2 * N_NODE + n];
    int deg = g_cnt[2 * N_NODE + n];
    if (deg == 0) return;
    int end = start + deg;
    float m0 = -3.4e38f, m1 = m0, m2 = m0, m3 = m0;
    for (int j = start + lane; j < end; j += 32) {
        int rd = g_sRidA[j];
        float a = g_sAlpha[j];
        float4 dr = *(const float4*)(g_dotRel + rd * 4);
        m0 = fmaxf(m0, a * dr.x); m1 = fmaxf(m1, a * dr.y);
        m2 = fmaxf(m2, a * dr.z); m3 = fmaxf(m3, a * dr.w);
    }
    m0 = wredmax(m0); m1 = wredmax(m1); m2 = wredmax(m2); m3 = wredmax(m3);
    float s0 = 0.f, s1 = 0.f, s2 = 0.f, s3 = 0.f;
    for (int j = start + lane; j < end; j += 32) {
        int rd = g_sRidA[j];
        float a = g_sAlpha[j];
        float4 dr = *(const float4*)(g_dotRel + rd * 4);
        float4 e;
        e.x = __expf(a * dr.x - m0); e.y = __expf(a * dr.y - m1);
        e.z = __expf(a * dr.z - m2); e.w = __expf(a * dr.w - m3);
        s0 += e.x; s1 += e.y; s2 += e.z; s3 += e.w;
        g_sW[j] = e;
    }
    s0 = wredsum(s0); s1 = wredsum(s1); s2 = wredsum(s2); s3 = wredsum(s3);
    float i0 = 1.f / s0, i1 = 1.f / s1, i2 = 1.f / s2, i3 = 1.f / s3;
    for (int j = start + lane; j < end; j += 32) {
        float4 e = g_sW[j];
        e.x *= i0; e.y *= i1; e.z *= i2; e.w *= i3;
        g_sW[j] = e;
    }
}

// fused heavy pass: both encoders, one layer. warp per node, gather.
__global__ void k_layer_fused(const float* __restrict__ rel_emb, int l) {
    int n = blockIdx.x * 8 + (threadIdx.x >> 5);
    if (n >= N_NODE) return;
    int lane = threadIdx.x & 31;
    int start = g_rowptr[2 * N_NODE + n];
    int deg = g_cnt[2 * N_NODE + n];
    int end = start + deg;
    float4 accE = make_float4(0.f, 0.f, 0.f, 0.f);
    float4 accR = make_float4(0.f, 0.f, 0.f, 0.f);
    const float* srcE = g_outE + l * DIM;
    const float* srcR = g_outR + l * DIM;
    for (int j = start; j < end; j++) {
        int col = g_sColA[j];
        int rd = g_sRidA[j];
        float a = g_sAlpha[j];
        float4 w4 = g_sW[j];
        float wE = (l == 0) ? w4.x : w4.y;
        float wR = (l == 0) ? w4.z : w4.w;
        float4 tr = *(const float4*)(rel_emb + rd * DIM + lane * 4);
        tr.x *= a; tr.y *= a; tr.z *= a; tr.w *= a;
        float4 hE = *(const float4*)(srcE + col * F3 + lane * 4);
        float4 hR = *(const float4*)(srcR + col * F3 + lane * 4);
        float dE = wredsum(dot4(hE, tr));
        float dR = wredsum(dot4(hR, tr));
        float cE = -2.f * wE * dE;
        float cR = -2.f * wR * dR;
        accE.x += wE * hE.x + cE * tr.x; accE.y += wE * hE.y + cE * tr.y;
        accE.z += wE * hE.z + cE * tr.z; accE.w += wE * hE.w + cE * tr.w;
        accR.x += wR * hR.x + cR * tr.x; accR.y += wR * hR.y + cR * tr.y;
        accR.z += wR * hR.z + cR * tr.z; accR.w += wR * hR.w + cR * tr.w;
    }
    float* dE = g_outE + n * F3 + (l + 1) * DIM + lane * 4;
    float* dR = g_outR + n * F3 + (l + 1) * DIM + lane * 4;
    dE[0] = tanhf(accE.x); dE[1] = tanhf(accE.y);
    dE[2] = tanhf(accE.z); dE[3] = tanhf(accE.w);
    dR[0] = tanhf(accR.x); dR[1] = tanhf(accR.y);
    dR[2] = tanhf(accR.z); dR[3] = tanhf(accR.w);
}

// ---------------- epilogue ----------------
__global__ void k_rownorm(int enc) {
    int n = blockIdx.x * 8 + (threadIdx.x >> 5);
    if (n >= N_NODE) return;
    int lane = threadIdx.x & 31;
    const float* p = (enc ? g_outR : g_outE) + n * F3;
    float ss = 0.f;
#pragma unroll
    for (int j = 0; j < 3; j++) {
        float4 v = *(const float4*)(p + j * 128 + lane * 4);
        ss += dot4(v, v);
    }
    ss = wredsum(ss);
    if (lane == 0) g_nrm[n] = fmaxf(sqrtf(ss), EPSF);
}

__global__ void k_pninv(const float* __restrict__ proxy) {
    int j = blockIdx.x * 8 + (threadIdx.x >> 5);
    if (j >= NP) return;
    int lane = threadIdx.x & 31;
    float ss = 0.f;
#pragma unroll
    for (int k = 0; k < 3; k++) {
        float4 v = *(const float4*)(proxy + j * F3 + k * 128 + lane * 4);
        ss += dot4(v, v);
    }
    ss = wredsum(ss);
    if (lane == 0) g_pninv[j] = 1.f / fmaxf(sqrtf(ss), EPSF);
}

// logits = out @ normalize(proxy)^T
__global__ void k_gemmA(const float* __restrict__ proxy, int enc) {
    __shared__ float As[16][64];
    __shared__ float Bs[16][64];
    const float* A = enc ? g_outR : g_outE;
    int bm = blockIdx.x * 64;
    int tid = threadIdx.x, tx = tid & 15, ty = tid >> 4;
    float acc[4][4] = {};
    for (int k0 = 0; k0 < F3; k0 += 16) {
        {
            int i = tid >> 2, kk = (tid & 3) << 2;
            float4 v = *(const float4*)(A + (bm + i) * F3 + k0 + kk);
            As[kk + 0][i] = v.x; As[kk + 1][i] = v.y; As[kk + 2][i] = v.z; As[kk + 3][i] = v.w;
            int n = tid >> 2;
            float s = g_pninv[n];
            float4 b = *(const float4*)(proxy + n * F3 + k0 + kk);
            Bs[kk + 0][n] = b.x * s; Bs[kk + 1][n] = b.y * s;
            Bs[kk + 2][n] = b.z * s; Bs[kk + 3][n] = b.w * s;
        }
        __syncthreads();
#pragma unroll
        for (int kk = 0; kk < 16; kk++) {
            float4 a4 = *(float4*)&As[kk][ty << 2];
            float4 b4 = *(float4*)&Bs[kk][tx << 2];
            float av[4] = { a4.x, a4.y, a4.z, a4.w };
            float bv[4] = { b4.x, b4.y, b4.z, b4.w };
#pragma unroll
            for (int r = 0; r < 4; r++)
#pragma unroll
                for (int cc = 0; cc < 4; cc++) acc[r][cc] += av[r] * bv[cc];
        }
        __syncthreads();
    }
#pragma unroll
    for (int r = 0; r < 4; r++) {
        int m = bm + (ty << 2) + r, n = tx << 2;
        *(float4*)(g_pa + m * NP + n) = make_float4(acc[r][0], acc[r][1], acc[r][2], acc[r][3]);
    }
}

__global__ void k_pa_softmax() {
    int n = blockIdx.x * 8 + (threadIdx.x >> 5);
    if (n >= N_NODE) return;
    int lane = threadIdx.x & 31;
    float inv = 1.f / g_nrm[n];
    float v0 = g_pa[n * NP + lane] * inv;
    float v1 = g_pa[n * NP + lane + 32] * inv;
    float m = wredmax(fmaxf(v0, v1));
    float e0 = __expf(v0 - m), e1 = __expf(v1 - m);
    float s = wredsum(e0 + e1);
    float is = 1.f / s;
    g_pa[n * NP + lane] = e0 * is;
    g_pa[n * NP + lane + 32] = e1 * is;
}

// pf = out - pa @ proxy
__global__ void k_gemmB(const float* __restrict__ proxy, int enc) {
    __shared__ float As[16][64];
    __shared__ float Bs[16][64];
    int bm = blockIdx.y * 64, bn = blockIdx.x * 64;
    int tid = threadIdx.x, tx = tid & 15, ty = tid >> 4;
    float acc[4][4] = {};
    for (int k0 = 0; k0 < NP; k0 += 16) {
        {
            int i = tid >> 2, kk = (tid & 3) << 2;
            float4 v = *(const float4*)(g_pa + (bm + i) * NP + k0 + kk);
            As[kk + 0][i] = v.x; As[kk + 1][i] = v.y; As[kk + 2][i] = v.z; As[kk + 3][i] = v.w;
            int kb = tid >> 4, n4 = (tid & 15) << 2;
            *(float4*)&Bs[kb][n4] = *(const float4*)(proxy + (k0 + kb) * F3 + bn + n4);
        }
        __syncthreads();
#pragma unroll
        for (int kk = 0; kk < 16; kk++) {
            float4 a4 = *(float4*)&As[kk][ty << 2];
            float4 b4 = *(float4*)&Bs[kk][tx << 2];
            float av[4] = { a4.x, a4.y, a4.z, a4.w };
            float bv[4] = { b4.x, b4.y, b4.z, b4.w };
#pragma unroll
            for (int r = 0; r < 4; r++)
#pragma unroll
                for (int cc = 0; cc < 4; cc++) acc[r][cc] += av[r] * bv[cc];
        }
        __syncthreads();
    }
    const float* outp = enc ? g_outR : g_outE;
#pragma unroll
    for (int r = 0; r < 4; r++) {
        int m = bm + (ty << 2) + r, n = bn + (tx << 2);
        float4 o = *(const float4*)(outp + m * F3 + n);
        *(float4*)(g_pf + m * F3 + n) = make_float4(o.x - acc[r][0], o.y - acc[r][1],
                                                    o.z - acc[r][2], o.w - acc[r][3]);
    }
}

// g = sigmoid(pf @ gate + bias); res = g*out + (1-g)*pf
__global__ void k_gemmC(const float* __restrict__ gate, const float* __restrict__ bias,
                        int enc, float* __restrict__ dout) {
    __shared__ float As[16][64];
    __shared__ float Bs[16][64];
    int bm = blockIdx.y * 64, bn = blockIdx.x * 64;
    int tid = threadIdx.x, tx = tid & 15, ty = tid >> 4;
    float acc[4][4] = {};
    for (int k0 = 0; k0 < F3; k0 += 16) {
        {
            int i = tid >> 2, kk = (tid & 3) << 2;
            float4 v = *(const float4*)(g_pf + (bm + i) * F3 + k0 + kk);
            As[kk + 0][i] = v.x; As[kk + 1][i] = v.y; As[kk + 2][i] = v.z; As[kk + 3][i] = v.w;
            int kb = tid >> 4, n4 = (tid & 15) << 2;
            *(float4*)&Bs[kb][n4] = *(const float4*)(gate + (k0 + kb) * F3 + bn + n4);
        }
        __syncthreads();
#pragma unroll
        for (int kk = 0; kk < 16; kk++) {
            float4 a4 = *(float4*)&As[kk][ty << 2];
            float4 b4 = *(float4*)&Bs[kk][tx << 2];
            float av[4] = { a4.x, a4.y, a4.z, a4.w };
            float bv[4] = { b4.x, b4.y, b4.z, b4.w };
#pragma unroll
            for (int r = 0; r < 4; r++)
#pragma unroll
                for (int cc = 0; cc < 4; cc++) acc[r][cc] += av[r] * bv[cc];
        }
        __syncthreads();
    }
    const float* outp = enc ? g_outR : g_outE;
#pragma unroll
    for (int r = 0; r < 4; r++) {
        int m = bm + (ty << 2) + r, n = bn + (tx << 2);
        float4 o = *(const float4*)(outp + m * F3 + n);
        float4 p = *(const float4*)(g_pf + m * F3 + n);
        float4 res;
        float z = acc[r][0] + bias[n + 0]; float g = 1.f / (1.f + __expf(-z));
        res.x = g * o.x + (1.f - g) * p.x;
        z = acc[r][1] + bias[n + 1]; g = 1.f / (1.f + __expf(-z));
        res.y = g * o.y + (1.f - g) * p.y;
        z = acc[r][2] + bias[n + 2]; g = 1.f / (1.f + __expf(-z));
        res.z = g * o.z + (1.f - g) * p.z;
        z = acc[r][3] + bias[n + 3]; g = 1.f / (1.f + __expf(-z));
        res.w = g * o.w + (1.f - g) * p.w;
        *(float4*)(dout + m * 768 + enc * F3 + n) = res;
    }
}

// ---------------- host ----------------
extern "C" void kernel_launch(void* const* d_in, const int* in_sizes, int n_in,
                              void* d_out, int out_size) {
    const int*   ent_adj = (const int*)d_in[0];
    const int*   rel_adj = (const int*)d_in[1];
    const int*   adj     = (const int*)d_in[4];
    const int*   r_index = (const int*)d_in[5];
    const float* r_val   = (const float*)d_in[6];
    const float* ent_emb = (const float*)d_in[9];
    const float* rel_emb = (const float*)d_in[10];
    const float* e_attn  = (const float*)d_in[11];
    const float* e_gate  = (const float*)d_in[12];
    const float* e_proxy = (const float*)d_in[13];
    const float* e_bias  = (const float*)d_in[14];
    const float* r_attn  = (const float*)d_in[15];
    const float* r_gate  = (const float*)d_in[16];
    const float* r_proxy = (const float*)d_in[17];
    const float* r_bias  = (const float*)d_in[18];
    float* out = (float*)d_out;

    const int* aRow = adj;
    const int* aCol = adj + T;
    const int* rid  = r_index + T;
    const int EB = (T + 255) / 256;  // 2344

    // CSR build for all three edge lists
    k_zero_cnt<<<(3 * N_NODE + 255) / 256, 256>>>();
    k_hist<<<EB, 256>>>(ent_adj, 0);
    k_hist<<<EB, 256>>>(rel_adj, 1);
    k_hist<<<EB, 256>>>(aRow, 2);
    for (int sel = 0; sel < 3; sel++) {
        k_scan1<<<SCAN_B, 256>>>(sel);
        k_scan2<<<1, 256>>>(sel);
        k_scan3<<<SCAN_B, 256>>>(sel);
    }
    k_rel_prep<<<250, 256>>>(rel_emb, e_attn, r_attn);
    k_scatter_col<<<EB, 256>>>(ent_adj, ent_adj + T, 0);
    k_scatter_col<<<EB, 256>>>(rel_adj, rel_adj + T, 1);
    k_scatterA<<<EB, 256>>>(aRow, aCol, rid, r_val);

    // initial averaged features (gather)
    k_avg_csr<<<5000, 256>>>(ent_emb, 0);
    k_avg_csr<<<5000, 256>>>(rel_emb, 1);

    // edge attention weights (all 4 combos)
    k_att_softmax<<<5000, 256>>>();

    // fused graph attention layers (both encoders per launch)
    k_layer_fused<<<5000, 256>>>(rel_emb, 0);
    k_layer_fused<<<5000, 256>>>(rel_emb, 1);

    // proxy/gate epilogue per encoder
    for (int enc = 0; enc < 2; enc++) {
        const float* proxy = enc ? r_proxy : e_proxy;
        const float* gate  = enc ? r_gate  : e_gate;
        const float* bias  = enc ? r_bias  : e_bias;
        k_rownorm<<<5000, 256>>>(enc);
        k_pninv<<<8, 256>>>(proxy);
        k_gemmA<<<625, 256>>>(proxy, enc);
        k_pa_softmax<<<5000, 256>>>();
        dim3 gB(6, 625);
        k_gemmB<<<gB, 256>>>(proxy, enc);
        k_gemmC<<<gB, 256>>>(gate, bias, enc, out);
    }
}

// round 4
// speedup vs baseline: 1.3395x; 1.0132x over previous
#include <cuda_runtime.h>
#include <cuda_bf16.h>
#include <mma.h>
#include <math.h>
#include <cstdint>

using namespace nvcuda;

#define N_NODE 40000
#define N_REL  2000
#define T      600000
#define DIM    128
#define F3     384
#define NP     64
#define EPSF   1e-12f
#define SCAN_B ((N_NODE + 255) / 256)   // 157

// ---------------- scratch (device globals; no allocation) ----------------
__device__ int    g_cnt[3 * N_NODE];
__device__ int    g_rowptr[3 * N_NODE];
__device__ int    g_cur[3 * N_NODE];
__device__ int    g_bsum[3 * 256];
__device__ int    g_sColE[T];
__device__ int    g_sColR[T];
__device__ int    g_sColA[T];
__device__ int    g_sRidA[T];
__device__ float  g_sAlpha[T];
__device__ float4 g_sW[T];

__device__ float g_outE[N_NODE * F3];
__device__ float g_outR[N_NODE * F3];
__device__ float g_pf[N_NODE * F3];
__device__ float g_pa[N_NODE * NP];
__device__ float g_nrm[N_NODE];
__device__ float g_relNorm[N_REL];
__device__ float g_dotRel[N_REL * 4];
__device__ float g_pninv[NP];

// bf16 split operands for tensor-core gemmC
__device__ __nv_bfloat16 g_pfh[N_NODE * F3];
__device__ __nv_bfloat16 g_pfl[N_NODE * F3];
__device__ __nv_bfloat16 g_gh[F3 * F3];   // gate hi  [k][n]
__device__ __nv_bfloat16 g_gl[F3 * F3];   // gate lo  [k][n]

// ---------------- generic helpers ----------------
__device__ __forceinline__ float wredsum(float v) {
#pragma unroll
    for (int o = 16; o; o >>= 1) v += __shfl_xor_sync(0xffffffffu, v, o);
    return v;
}
__device__ __forceinline__ float wredmax(float v) {
#pragma unroll
    for (int o = 16; o; o >>= 1) v = fmaxf(v, __shfl_xor_sync(0xffffffffu, v, o));
    return v;
}
__device__ __forceinline__ float dot4(float4 a, float4 b) {
    return a.x * b.x + a.y * b.y + a.z * b.z + a.w * b.w;
}

// ---------------- CSR build ----------------
__global__ void k_zero_cnt() {
    int i = blockIdx.x * blockDim.x + threadIdx.x;
    if (i < 3 * N_NODE) g_cnt[i] = 0;
}
__global__ void k_hist(const int* __restrict__ rows, int sel) {
    int t = blockIdx.x * blockDim.x + threadIdx.x;
    if (t < T) atomicAdd(&g_cnt[sel * N_NODE + rows[t]], 1);
}
__global__ void k_scan1(int sel) {
    __shared__ int sh[256];
    int tid = threadIdx.x;
    int i = blockIdx.x * 256 + tid;
    int v = (i < N_NODE) ? g_cnt[sel * N_NODE + i] : 0;
    int x = v;
    sh[tid] = x; __syncthreads();
#pragma unroll
    for (int o = 1; o < 256; o <<= 1) {
        int t = (tid >= o) ? sh[tid - o] : 0;
        __syncthreads();
        x += t; sh[tid] = x;
        __syncthreads();
    }
    if (i < N_NODE) g_rowptr[sel * N_NODE + i] = x - v;
    if (tid == 255) g_bsum[sel * 256 + blockIdx.x] = x;
}
__global__ void k_scan2(int sel) {
    __shared__ int sh[256];
    int tid = threadIdx.x;
    int v = (tid < SCAN_B) ? g_bsum[sel * 256 + tid] : 0;
    int x = v;
    sh[tid] = x; __syncthreads();
#pragma unroll
    for (int o = 1; o < 256; o <<= 1) {
        int t = (tid >= o) ? sh[tid - o] : 0;
        __syncthreads();
        x += t; sh[tid] = x;
        __syncthreads();
    }
    g_bsum[sel * 256 + tid] = x - v;
}
__global__ void k_scan3(int sel) {
    int i = blockIdx.x * blockDim.x + threadIdx.x;
    if (i >= N_NODE) return;
    int val = g_rowptr[sel * N_NODE + i] + g_bsum[sel * 256 + (i >> 8)];
    g_rowptr[sel * N_NODE + i] = val;
    g_cur[sel * N_NODE + i] = val;
}
__global__ void k_scatter_col(const int* __restrict__ rows, const int* __restrict__ cols,
                              int sel) {
    int t = blockIdx.x * blockDim.x + threadIdx.x;
    if (t >= T) return;
    int pos = atomicAdd(&g_cur[sel * N_NODE + rows[t]], 1);
    (sel == 0 ? g_sColE : g_sColR)[pos] = cols[t];
}
__global__ void k_scatterA(const int* __restrict__ rows, const int* __restrict__ cols,
                           const int* __restrict__ rid, const float* __restrict__ rval) {
    int t = blockIdx.x * blockDim.x + threadIdx.x;
    if (t >= T) return;
    int pos = atomicAdd(&g_cur[2 * N_NODE + rows[t]], 1);
    int rd = rid[t];
    float rv = rval[t];
    g_sColA[pos] = cols[t];
    g_sRidA[pos] = rd;
    g_sAlpha[pos] = rv / fmaxf(rv * g_relNorm[rd], EPSF);
}

__global__ void k_rel_prep(const float* __restrict__ rel_emb,
                           const float* __restrict__ eattn,
                           const float* __restrict__ rattn) {
    int w = blockIdx.x * 8 + (threadIdx.x >> 5);
    if (w >= N_REL) return;
    int lane = threadIdx.x & 31;
    float4 v  = *(const float4*)(rel_emb + w * DIM + lane * 4);
    float4 a0 = *(const float4*)(eattn + lane * 4);
    float4 a1 = *(const float4*)(eattn + 128 + lane * 4);
    float4 a2 = *(const float4*)(rattn + lane * 4);
    float4 a3 = *(const float4*)(rattn + 128 + lane * 4);
    float ss = wredsum(dot4(v, v));
    float d0 = wredsum(dot4(v, a0));
    float d1 = wredsum(dot4(v, a1));
    float d2 = wredsum(dot4(v, a2));
    float d3 = wredsum(dot4(v, a3));
    if (lane == 0) {
        g_relNorm[w] = sqrtf(ss);
        g_dotRel[w * 4 + 0] = d0; g_dotRel[w * 4 + 1] = d1;
        g_dotRel[w * 4 + 2] = d2; g_dotRel[w * 4 + 3] = d3;
    }
}

__global__ void k_avg_csr(const float* __restrict__ emb, int sel) {
    int n = blockIdx.x * 8 + (threadIdx.x >> 5);
    if (n >= N_NODE) return;
    int lane = threadIdx.x & 31;
    int start = g_rowptr[sel * N_NODE + n];
    int deg = g_cnt[sel * N_NODE + n];
    const int* scol = sel == 0 ? g_sColE : g_sColR;
    float4 acc = make_float4(0.f, 0.f, 0.f, 0.f);
    for (int j = start; j < start + deg; j++) {
        int c = scol[j];
        float4 v = *(const float4*)(emb + c * DIM + lane * 4);
        acc.x += v.x; acc.y += v.y; acc.z += v.z; acc.w += v.w;
    }
    float inv = deg > 0 ? 1.f / (float)deg : 0.f;
    float* dst = (sel == 0 ? g_outE : g_outR) + n * F3 + lane * 4;
    dst[0] = tanhf(acc.x * inv);
    dst[1] = tanhf(acc.y * inv);
    dst[2] = tanhf(acc.z * inv);
    dst[3] = tanhf(acc.w * inv);
}

__global__ void k_att_softmax() {
    int n = blockIdx.x * 8 + (threadIdx.x >> 5);
    if (n >= N_NODE) return;
    int lane = threadIdx.x & 31;
    int start = g_rowptr[2 * N_NODE + n];
    int deg = g_cnt[2 * N_NODE + n];
    if (deg == 0) return;
    int end = start + deg;
    float m0 = -3.4e38f, m1 = m0, m2 = m0, m3 = m0;
    for (int j = start + lane; j < end; j += 32) {
        int rd = g_sRidA[j];
        float a = g_sAlpha[j];
        float4 dr = *(const float4*)(g_dotRel + rd * 4);
        m0 = fmaxf(m0, a * dr.x); m1 = fmaxf(m1, a * dr.y);
        m2 = fmaxf(m2, a * dr.z); m3 = fmaxf(m3, a * dr.w);
    }
    m0 = wredmax(m0); m1 = wredmax(m1); m2 = wredmax(m2); m3 = wredmax(m3);
    float s0 = 0.f, s1 = 0.f, s2 = 0.f, s3 = 0.f;
    for (int j = start + lane; j < end; j += 32) {
        int rd = g_sRidA[j];
        float a = g_sAlpha[j];
        float4 dr = *(const float4*)(g_dotRel + rd * 4);
        float4 e;
        e.x = __expf(a * dr.x - m0); e.y = __expf(a * dr.y - m1);
        e.z = __expf(a * dr.z - m2); e.w = __expf(a * dr.w - m3);
        s0 += e.x; s1 += e.y; s2 += e.z; s3 += e.w;
        g_sW[j] = e;
    }
    s0 = wredsum(s0); s1 = wredsum(s1); s2 = wredsum(s2); s3 = wredsum(s3);
    float i0 = 1.f / s0, i1 = 1.f / s1, i2 = 1.f / s2, i3 = 1.f / s3;
    for (int j = start + lane; j < end; j += 32) {
        float4 e = g_sW[j];
        e.x *= i0; e.y *= i1; e.z *= i2; e.w *= i3;
        g_sW[j] = e;
    }
}

__global__ void k_layer_fused(const float* __restrict__ rel_emb, int l) {
    int n = blockIdx.x * 8 + (threadIdx.x >> 5);
    if (n >= N_NODE) return;
    int lane = threadIdx.x & 31;
    int start = g_rowptr[2 * N_NODE + n];
    int deg = g_cnt[2 * N_NODE + n];
    int end = start + deg;
    float4 accE = make_float4(0.f, 0.f, 0.f, 0.f);
    float4 accR = make_float4(0.f, 0.f, 0.f, 0.f);
    const float* srcE = g_outE + l * DIM;
    const float* srcR = g_outR + l * DIM;
    for (int j = start; j < end; j++) {
        int col = g_sColA[j];
        int rd = g_sRidA[j];
        float a = g_sAlpha[j];
        float4 w4 = g_sW[j];
        float wE = (l == 0) ? w4.x : w4.y;
        float wR = (l == 0) ? w4.z : w4.w;
        float4 tr = *(const float4*)(rel_emb + rd * DIM + lane * 4);
        tr.x *= a; tr.y *= a; tr.z *= a; tr.w *= a;
        float4 hE = *(const float4*)(srcE + col * F3 + lane * 4);
        float4 hR = *(const float4*)(srcR + col * F3 + lane * 4);
        float dE = wredsum(dot4(hE, tr));
        float dR = wredsum(dot4(hR, tr));
        float cE = -2.f * wE * dE;
        float cR = -2.f * wR * dR;
        accE.x += wE * hE.x + cE * tr.x; accE.y += wE * hE.y + cE * tr.y;
        accE.z += wE * hE.z + cE * tr.z; accE.w += wE * hE.w + cE * tr.w;
        accR.x += wR * hR.x + cR * tr.x; accR.y += wR * hR.y + cR * tr.y;
        accR.z += wR * hR.z + cR * tr.z; accR.w += wR * hR.w + cR * tr.w;
    }
    float* dE = g_outE + n * F3 + (l + 1) * DIM + lane * 4;
    float* dR = g_outR + n * F3 + (l + 1) * DIM + lane * 4;
    dE[0] = tanhf(accE.x); dE[1] = tanhf(accE.y);
    dE[2] = tanhf(accE.z); dE[3] = tanhf(accE.w);
    dR[0] = tanhf(accR.x); dR[1] = tanhf(accR.y);
    dR[2] = tanhf(accR.z); dR[3] = tanhf(accR.w);
}

// ---------------- epilogue ----------------
__global__ void k_rownorm(int enc) {
    int n = blockIdx.x * 8 + (threadIdx.x >> 5);
    if (n >= N_NODE) return;
    int lane = threadIdx.x & 31;
    const float* p = (enc ? g_outR : g_outE) + n * F3;
    float ss = 0.f;
#pragma unroll
    for (int j = 0; j < 3; j++) {
        float4 v = *(const float4*)(p + j * 128 + lane * 4);
        ss += dot4(v, v);
    }
    ss = wredsum(ss);
    if (lane == 0) g_nrm[n] = fmaxf(sqrtf(ss), EPSF);
}

__global__ void k_pninv(const float* __restrict__ proxy) {
    int j = blockIdx.x * 8 + (threadIdx.x >> 5);
    if (j >= NP) return;
    int lane = threadIdx.x & 31;
    float ss = 0.f;
#pragma unroll
    for (int k = 0; k < 3; k++) {
        float4 v = *(const float4*)(proxy + j * F3 + k * 128 + lane * 4);
        ss += dot4(v, v);
    }
    ss = wredsum(ss);
    if (lane == 0) g_pninv[j] = 1.f / fmaxf(sqrtf(ss), EPSF);
}

__global__ void k_gemmA(const float* __restrict__ proxy, int enc) {
    __shared__ float As[16][64];
    __shared__ float Bs[16][64];
    const float* A = enc ? g_outR : g_outE;
    int bm = blockIdx.x * 64;
    int tid = threadIdx.x, tx = tid & 15, ty = tid >> 4;
    float acc[4][4] = {};
    for (int k0 = 0; k0 < F3; k0 += 16) {
        {
            int i = tid >> 2, kk = (tid & 3) << 2;
            float4 v = *(const float4*)(A + (bm + i) * F3 + k0 + kk);
            As[kk + 0][i] = v.x; As[kk + 1][i] = v.y; As[kk + 2][i] = v.z; As[kk + 3][i] = v.w;
            int n = tid >> 2;
            float s = g_pninv[n];
            float4 b = *(const float4*)(proxy + n * F3 + k0 + kk);
            Bs[kk + 0][n] = b.x * s; Bs[kk + 1][n] = b.y * s;
            Bs[kk + 2][n] = b.z * s; Bs[kk + 3][n] = b.w * s;
        }
        __syncthreads();
#pragma unroll
        for (int kk = 0; kk < 16; kk++) {
            float4 a4 = *(float4*)&As[kk][ty << 2];
            float4 b4 = *(float4*)&Bs[kk][tx << 2];
            float av[4] = { a4.x, a4.y, a4.z, a4.w };
            float bv[4] = { b4.x, b4.y, b4.z, b4.w };
#pragma unroll
            for (int r = 0; r < 4; r++)
#pragma unroll
                for (int cc = 0; cc < 4; cc++) acc[r][cc] += av[r] * bv[cc];
        }
        __syncthreads();
    }
#pragma unroll
    for (int r = 0; r < 4; r++) {
        int m = bm + (ty << 2) + r, n = tx << 2;
        *(float4*)(g_pa + m * NP + n) = make_float4(acc[r][0], acc[r][1], acc[r][2], acc[r][3]);
    }
}

__global__ void k_pa_softmax() {
    int n = blockIdx.x * 8 + (threadIdx.x >> 5);
    if (n >= N_NODE) return;
    int lane = threadIdx.x & 31;
    float inv = 1.f / g_nrm[n];
    float v0 = g_pa[n * NP + lane] * inv;
    float v1 = g_pa[n * NP + lane + 32] * inv;
    float m = wredmax(fmaxf(v0, v1));
    float e0 = __expf(v0 - m), e1 = __expf(v1 - m);
    float s = wredsum(e0 + e1);
    float is = 1.f / s;
    g_pa[n * NP + lane] = e0 * is;
    g_pa[n * NP + lane + 32] = e1 * is;
}

// pf = out - pa @ proxy   (+ bf16 hi/lo split emission)
__global__ void k_gemmB(const float* __restrict__ proxy, int enc) {
    __shared__ float As[16][64];
    __shared__ float Bs[16][64];
    int bm = blockIdx.y * 64, bn = blockIdx.x * 64;
    int tid = threadIdx.x, tx = tid & 15, ty = tid >> 4;
    float acc[4][4] = {};
    for (int k0 = 0; k0 < NP; k0 += 16) {
        {
            int i = tid >> 2, kk = (tid & 3) << 2;
            float4 v = *(const float4*)(g_pa + (bm + i) * NP + k0 + kk);
            As[kk + 0][i] = v.x; As[kk + 1][i] = v.y; As[kk + 2][i] = v.z; As[kk + 3][i] = v.w;
            int kb = tid >> 4, n4 = (tid & 15) << 2;
            *(float4*)&Bs[kb][n4] = *(const float4*)(proxy + (k0 + kb) * F3 + bn + n4);
        }
        __syncthreads();
#pragma unroll
        for (int kk = 0; kk < 16; kk++) {
            float4 a4 = *(float4*)&As[kk][ty << 2];
            float4 b4 = *(float4*)&Bs[kk][tx << 2];
            float av[4] = { a4.x, a4.y, a4.z, a4.w };
            float bv[4] = { b4.x, b4.y, b4.z, b4.w };
#pragma unroll
            for (int r = 0; r < 4; r++)
#pragma unroll
                for (int cc = 0; cc < 4; cc++) acc[r][cc] += av[r] * bv[cc];
        }
        __syncthreads();
    }
    const float* outp = enc ? g_outR : g_outE;
#pragma unroll
    for (int r = 0; r < 4; r++) {
        int m = bm + (ty << 2) + r, n = bn + (tx << 2);
        float4 o = *(const float4*)(outp + m * F3 + n);
        float4 v = make_float4(o.x - acc[r][0], o.y - acc[r][1],
                               o.z - acc[r][2], o.w - acc[r][3]);
        *(float4*)(g_pf + m * F3 + n) = v;
        float vv[4] = { v.x, v.y, v.z, v.w };
#pragma unroll
        for (int q = 0; q < 4; q++) {
            __nv_bfloat16 h = __float2bfloat16(vv[q]);
            g_pfh[m * F3 + n + q] = h;
            g_pfl[m * F3 + n + q] = __float2bfloat16(vv[q] - __bfloat162float(h));
        }
    }
}

// split the gate matrix (keep [k][n] layout): g_g*[k][n] = split(gate[k][n])
__global__ void k_gate_split(const float* __restrict__ gate) {
    int i = blockIdx.x * blockDim.x + threadIdx.x;
    if (i >= F3 * F3) return;
    float v = gate[i];
    __nv_bfloat16 h = __float2bfloat16(v);
    g_gh[i] = h;
    g_gl[i] = __float2bfloat16(v - __bfloat162float(h));
}

// ---------------- wmma gemmC: z = pf @ gate (3-term bf16 split) ----------------
#define A_ST 48     // row stride (elements) of A smem tiles
#define B_ST 144    // row stride (elements) of B smem tiles
#define GC_SMEM 65536

__global__ __launch_bounds__(256, 1) void k_gemmC_mma(const float* __restrict__ bias,
                                                      int enc, float* __restrict__ dout) {
    extern __shared__ __align__(16) char sm[];
    __nv_bfloat16* sAh = (__nv_bfloat16*)sm;                    // 128*48*2 = 12288
    __nv_bfloat16* sAl = (__nv_bfloat16*)(sm + 12288);          // 12288
    __nv_bfloat16* sBh = (__nv_bfloat16*)(sm + 24576);          // 32*144*2 = 9216
    __nv_bfloat16* sBl = (__nv_bfloat16*)(sm + 33792);          // 9216
    float* epi = (float*)sm;                                    // reused: 128*128*4 = 65536

    int tid = threadIdx.x, wid = tid >> 5;
    int bm = blockIdx.y * 128, bn = blockIdx.x * 128;
    int moff = (wid & 3) << 5;    // warp M offset 0/32/64/96
    int noff = (wid >> 2) << 6;   // warp N offset 0/64

    wmma::fragment<wmma::accumulator, 16, 16, 16, float> acc[2][4];
#pragma unroll
    for (int mi = 0; mi < 2; mi++)
#pragma unroll
        for (int ni = 0; ni < 4; ni++) wmma::fill_fragment(acc[mi][ni], 0.f);

    for (int kt = 0; kt < 12; kt++) {
        int k0 = kt * 32;
        // A tiles: [128][32] hi/lo
#pragma unroll
        for (int j = 0; j < 2; j++) {
            int i = tid + j * 256;            // 0..511
            int r = i >> 2, c = (i & 3) << 3; // col in 8-elt units
            int grow = bm + r;
            uint4 vh = make_uint4(0, 0, 0, 0), vl = vh;
            if (grow < N_NODE) {
                vh = *(const uint4*)(g_pfh + grow * F3 + k0 + c);
                vl = *(const uint4*)(g_pfl + grow * F3 + k0 + c);
            }
            *(uint4*)(sAh + r * A_ST + c) = vh;
            *(uint4*)(sAl + r * A_ST + c) = vl;
        }
        // B tiles: [32][128] hi/lo
#pragma unroll
        for (int j = 0; j < 2; j++) {
            int i = tid + j * 256;
            int r = i >> 4, c = (i & 15) << 3;
            *(uint4*)(sBh + r * B_ST + c) = *(const uint4*)(g_gh + (k0 + r) * F3 + bn + c);
            *(uint4*)(sBl + r * B_ST + c) = *(const uint4*)(g_gl + (k0 + r) * F3 + bn + c);
        }
        __syncthreads();
#pragma unroll
        for (int ks = 0; ks < 2; ks++) {
            wmma::fragment<wmma::matrix_a, 16, 16, 16, __nv_bfloat16, wmma::row_major> ah[2], al[2];
            wmma::fragment<wmma::matrix_b, 16, 16, 16, __nv_bfloat16, wmma::row_major> bh[4], bl[4];
#pragma unroll
            for (int mi = 0; mi < 2; mi++) {
                wmma::load_matrix_sync(ah[mi], sAh + (moff + mi * 16) * A_ST + ks * 16, A_ST);
                wmma::load_matrix_sync(al[mi], sAl + (moff + mi * 16) * A_ST + ks * 16, A_ST);
            }
#pragma unroll
            for (int ni = 0; ni < 4; ni++) {
                wmma::load_matrix_sync(bh[ni], sBh + (ks * 16) * B_ST + noff + ni * 16, B_ST);
                wmma::load_matrix_sync(bl[ni], sBl + (ks * 16) * B_ST + noff + ni * 16, B_ST);
            }
#pragma unroll
            for (int mi = 0; mi < 2; mi++)
#pragma unroll
                for (int ni = 0; ni < 4; ni++) {
                    wmma::mma_sync(acc[mi][ni], ah[mi], bh[ni], acc[mi][ni]);
                    wmma::mma_sync(acc[mi][ni], al[mi], bh[ni], acc[mi][ni]);
                    wmma::mma_sync(acc[mi][ni], ah[mi], bl[ni], acc[mi][ni]);
                }
        }
        __syncthreads();
    }

    // stage accumulators to smem
#pragma unroll
    for (int mi = 0; mi < 2; mi++)
#pragma unroll
        for (int ni = 0; ni < 4; ni++)
            wmma::store_matrix_sync(epi + (moff + mi * 16) * 128 + noff + ni * 16,
                                    acc[mi][ni], 128, wmma::mem_row_major);
    __syncthreads();

    // fused sigmoid-gate epilogue
    const float* outp = enc ? g_outR : g_outE;
#pragma unroll
    for (int j = 0; j < 16; j++) {
        int i = tid + j * 256;                // 0..4095 float4 units
        int r = i >> 5, c = (i & 31) << 2;    // 32 float4 per 128-col row
        int row = bm + r;
        if (row >= N_NODE) continue;
        int col = bn + c;
        float4 z4 = *(float4*)(epi + r * 128 + c);
        float4 o = *(const float4*)(outp + row * F3 + col);
        float4 p = *(const float4*)(g_pf + row * F3 + col);
        float4 b = *(const float4*)(bias + col);
        float z, g;
        float4 res;
        z = z4.x + b.x; g = 1.f / (1.f + __expf(-z)); res.x = g * o.x + (1.f - g) * p.x;
        z = z4.y + b.y; g = 1.f / (1.f + __expf(-z)); res.y = g * o.y + (1.f - g) * p.y;
        z = z4.z + b.z; g = 1.f / (1.f + __expf(-z)); res.z = g * o.z + (1.f - g) * p.z;
        z = z4.w + b.w; g = 1.f / (1.f + __expf(-z)); res.w = g * o.w + (1.f - g) * p.w;
        *(float4*)(dout + row * 768 + enc * F3 + col) = res;
    }
}

// ---------------- host ----------------
extern "C" void kernel_launch(void* const* d_in, const int* in_sizes, int n_in,
                              void* d_out, int out_size) {
    const int*   ent_adj = (const int*)d_in[0];
    const int*   rel_adj = (const int*)d_in[1];
    const int*   adj     = (const int*)d_in[4];
    const int*   r_index = (const int*)d_in[5];
    const float* r_val   = (const float*)d_in[6];
    const float* ent_emb = (const float*)d_in[9];
    const float* rel_emb = (const float*)d_in[10];
    const float* e_attn  = (const float*)d_in[11];
    const float* e_gate  = (const float*)d_in[12];
    const float* e_proxy = (const float*)d_in[13];
    const float* e_bias  = (const float*)d_in[14];
    const float* r_attn  = (const float*)d_in[15];
    const float* r_gate  = (const float*)d_in[16];
    const float* r_proxy = (const float*)d_in[17];
    const float* r_bias  = (const float*)d_in[18];
    float* out = (float*)d_out;

    cudaFuncSetAttribute(k_gemmC_mma, cudaFuncAttributeMaxDynamicSharedMemorySize, GC_SMEM);

    const int* aRow = adj;
    const int* aCol = adj + T;
    const int* rid  = r_index + T;
    const int EB = (T + 255) / 256;

    k_zero_cnt<<<(3 * N_NODE + 255) / 256, 256>>>();
    k_hist<<<EB, 256>>>(ent_adj, 0);
    k_hist<<<EB, 256>>>(rel_adj, 1);
    k_hist<<<EB, 256>>>(aRow, 2);
    for (int sel = 0; sel < 3; sel++) {
        k_scan1<<<SCAN_B, 256>>>(sel);
        k_scan2<<<1, 256>>>(sel);
        k_scan3<<<SCAN_B, 256>>>(sel);
    }
    k_rel_prep<<<250, 256>>>(rel_emb, e_attn, r_attn);
    k_scatter_col<<<EB, 256>>>(ent_adj, ent_adj + T, 0);
    k_scatter_col<<<EB, 256>>>(rel_adj, rel_adj + T, 1);
    k_scatterA<<<EB, 256>>>(aRow, aCol, rid, r_val);

    k_avg_csr<<<5000, 256>>>(ent_emb, 0);
    k_avg_csr<<<5000, 256>>>(rel_emb, 1);

    k_att_softmax<<<5000, 256>>>();

    k_layer_fused<<<5000, 256>>>(rel_emb, 0);
    k_layer_fused<<<5000, 256>>>(rel_emb, 1);

    for (int enc = 0; enc < 2; enc++) {
        const float* proxy = enc ? r_proxy : e_proxy;
        const float* gate  = enc ? r_gate  : e_gate;
        const float* bias  = enc ? r_bias  : e_bias;
        k_rownorm<<<5000, 256>>>(enc);
        k_pninv<<<8, 256>>>(proxy);
        k_gemmA<<<625, 256>>>(proxy, enc);
        k_pa_softmax<<<5000, 256>>>();
        dim3 gB(6, 625);
        k_gemmB<<<gB, 256>>>(proxy, enc);
        k_gate_split<<<(F3 * F3 + 255) / 256, 256>>>(gate);
        dim3 gC(3, 313);
        k_gemmC_mma<<<gC, 256, GC_SMEM>>>(bias, enc, out);
    }
}